// round 1
// baseline (speedup 1.0000x reference)
#include <cuda_runtime.h>
#include <stdint.h>

// ============================================================================
// SpecAugment on GPU, bit-exact vs JAX threefry2x32 (partitionable mode).
//
// Shapes: mel [64, 80, 4000] f32, lengths [64] int32. Output same as mel with
// freq-mask rows and time-mask columns zeroed.
//
// RNG derivation (jax_threefry_partitionable = True, default since JAX 0.4.36):
//   base = key(42) = (0, 42)
//   split(base, 4) fold-like:   key_j   = threefry(base, (0, j)),  j=0..3
//     kf_w=key0, kf_s=key1, kt_w=key2, kt_s=key3
//   randint(kf_w, (64,2), 0, 16):
//     k2 = threefry(kf_w, (0,1))   (second fold-like split key)
//     span=16 divides 2^16 => multiplier==0 => f = (randbits(k2)[b,j]) % 16
//   random_bits(key, 32, shape)[i] = o0 ^ o1, (o0,o1)=threefry(key,(0,i)),
//     i = row-major flat index
//   uniform(bits) = bitcast((bits>>9) | 0x3f800000) - 1.0f
// ============================================================================

#define BATCH 64
#define NMELS 80
#define TLEN 4000

__device__ int g_fm0[BATCH][2];  // freq mask start
__device__ int g_fml[BATCH][2];  // freq mask length
__device__ int g_tm0[BATCH][5];  // time mask start
__device__ int g_tml[BATCH][5];  // time mask length

__device__ __forceinline__ uint32_t rotl32(uint32_t x, int d) {
    return (x << d) | (x >> (32 - d));
}

__device__ __forceinline__ void tf2x32(uint32_t k0, uint32_t k1,
                                       uint32_t c0, uint32_t c1,
                                       uint32_t& o0, uint32_t& o1) {
    const uint32_t ks0 = k0, ks1 = k1, ks2 = 0x1BD11BDAu ^ k0 ^ k1;
    uint32_t x0 = c0 + ks0, x1 = c1 + ks1;
#define TF_RND(r) { x0 += x1; x1 = rotl32(x1, r); x1 ^= x0; }
    TF_RND(13) TF_RND(15) TF_RND(26) TF_RND(6)
    x0 += ks1; x1 += ks2 + 1u;
    TF_RND(17) TF_RND(29) TF_RND(16) TF_RND(24)
    x0 += ks2; x1 += ks0 + 2u;
    TF_RND(13) TF_RND(15) TF_RND(26) TF_RND(6)
    x0 += ks0; x1 += ks1 + 3u;
    TF_RND(17) TF_RND(29) TF_RND(16) TF_RND(24)
    x0 += ks1; x1 += ks2 + 4u;
    TF_RND(13) TF_RND(15) TF_RND(26) TF_RND(6)
    x0 += ks2; x1 += ks0 + 5u;
#undef TF_RND
    o0 = x0; o1 = x1;
}

// random_bits (partitionable, 32-bit): xor of the threefry output pair
__device__ __forceinline__ uint32_t randbits32(uint32_t k0, uint32_t k1, uint32_t idx) {
    uint32_t a, b;
    tf2x32(k0, k1, 0u, idx, a, b);
    return a ^ b;
}

__device__ __forceinline__ float u32_to_unif(uint32_t bits) {
    return __uint_as_float((bits >> 9) | 0x3f800000u) - 1.0f;
}

__global__ void mask_kernel(const int* __restrict__ lengths) {
    int b = threadIdx.x;
    if (b >= BATCH) return;

    // fold-like split of key(42) = (0, 42) into 4 keys
    uint32_t kfw0, kfw1, kfs0, kfs1, ktw0, ktw1, kts0, kts1;
    tf2x32(0u, 42u, 0u, 0u, kfw0, kfw1);
    tf2x32(0u, 42u, 0u, 1u, kfs0, kfs1);
    tf2x32(0u, 42u, 0u, 2u, ktw0, ktw1);
    tf2x32(0u, 42u, 0u, 3u, kts0, kts1);
    // randint's internal split of kf_w: we need only k2 (lower bits key)
    uint32_t klo0, klo1;
    tf2x32(kfw0, kfw1, 0u, 1u, klo0, klo1);

    // ---- frequency masks ----
#pragma unroll
    for (int j = 0; j < 2; j++) {
        uint32_t i = (uint32_t)(b * 2 + j);
        int f = (int)(randbits32(klo0, klo1, i) & 15u);       // randint [0,16)
        float uf = u32_to_unif(randbits32(kfs0, kfs1, i));
        int f0 = (int)floorf(uf * (float)(NMELS - f + 1));
        g_fm0[b][j] = f0;
        g_fml[b][j] = f;
    }

    // ---- time masks ----
    int valid = lengths[b];
    int mt = (int)((float)valid * 0.05f);        // astype(int32): trunc toward 0
    int max_t = min(25, mt);
    max_t = min(max_t, valid - 1);
    max_t = max(0, max_t);
#pragma unroll
    for (int j = 0; j < 5; j++) {
        uint32_t i = (uint32_t)(b * 5 + j);
        float ut = u32_to_unif(randbits32(ktw0, ktw1, i));
        int t = (int)floorf(ut * (float)(max_t + 1));
        if (valid <= 1) t = 0;
        float ut0 = u32_to_unif(randbits32(kts0, kts1, i));
        int t0 = (int)floorf(ut0 * (float)(valid - t + 1));
        g_tm0[b][j] = t0;
        g_tml[b][j] = t;
    }
}

// One float4 per thread. grid = (ceil(1000/256), B*NMELS)
__global__ void __launch_bounds__(256) apply_kernel(const float* __restrict__ mel,
                                                    float* __restrict__ out) {
    int row = blockIdx.y;            // b * NMELS + m
    int b = row / NMELS;
    int m = row - b * NMELS;
    int i = blockIdx.x * 256 + threadIdx.x;
    if (i >= TLEN / 4) return;
    int t = i * 4;
    size_t off = (size_t)row * TLEN + t;

    float4 v = *reinterpret_cast<const float4*>(mel + off);

    bool rowzero = ((unsigned)(m - g_fm0[b][0]) < (unsigned)g_fml[b][0]) |
                   ((unsigned)(m - g_fm0[b][1]) < (unsigned)g_fml[b][1]);
    if (rowzero) {
        v.x = 0.f; v.y = 0.f; v.z = 0.f; v.w = 0.f;
    } else {
        unsigned z0 = 0, z1 = 0, z2 = 0, z3 = 0;
#pragma unroll
        for (int j = 0; j < 5; j++) {
            int t0 = g_tm0[b][j];
            unsigned len = (unsigned)g_tml[b][j];
            z0 |= ((unsigned)(t     - t0) < len);
            z1 |= ((unsigned)(t + 1 - t0) < len);
            z2 |= ((unsigned)(t + 2 - t0) < len);
            z3 |= ((unsigned)(t + 3 - t0) < len);
        }
        if (z0) v.x = 0.f;
        if (z1) v.y = 0.f;
        if (z2) v.z = 0.f;
        if (z3) v.w = 0.f;
    }
    *reinterpret_cast<float4*>(out + off) = v;
}

extern "C" void kernel_launch(void* const* d_in, const int* in_sizes, int n_in,
                              void* d_out, int out_size) {
    const float* mel = (const float*)d_in[0];
    const int* lengths = (const int*)d_in[1];
    float* out = (float*)d_out;

    mask_kernel<<<1, 64>>>(lengths);
    dim3 grid((TLEN / 4 + 255) / 256, BATCH * NMELS);
    apply_kernel<<<grid, 256>>>(mel, out);
}